// round 1
// baseline (speedup 1.0000x reference)
#include <cuda_runtime.h>
#include <cooperative_groups.h>
#include <math.h>

namespace cg = cooperative_groups;

#define T_STEPS 32768
#define DIM 256
#define G3 768            // 3*DIM
#define FFN_DIM 1024
#define NC 8              // cluster size (CTAs)
#define SCAN_THREADS 384  // 12 warps, 96 cols x 4 threads/col

// ---------------- scratch (static device allocations; no cudaMalloc allowed) ----
__device__ float g_xg[T_STEPS * G3];     // xs @ Wi            (100.7 MB)
__device__ float g_ys[T_STEPS * DIM];    // GRU outputs h_t    (33.6 MB)
__device__ float g_t3[T_STEPS * DIM];    // relu(ys)@Wg + bg   (33.6 MB)
__device__ float g_y [T_STEPS * DIM];    // LN1 output         (33.6 MB)
__device__ float g_t1[T_STEPS * FFN_DIM];// relu(y@W1+b1)      (134 MB)
__device__ float g_t6[T_STEPS * DIM];    // t1@W2 + b2         (33.6 MB)

// ---------------- fast transcendentals (fp32, ~1e-6 rel err) --------------------
__device__ __forceinline__ float sigmoid_fast(float x) {
    return __fdividef(1.f, 1.f + __expf(-x));
}
__device__ __forceinline__ float tanh_fast(float x) {
    // (e^{2x}-1)/(e^{2x}+1); saturates gracefully at +-1 via inf/0
    float e = __expf(2.f * x);
    return 1.f - __fdividef(2.f, e + 1.f);
}

// ================================================================================
// GRU scan: one 8-CTA cluster. CTA c owns h indices [c*32, c*32+32) and the 96
// Wh columns {g*256 + c*32 + m}. Weights live in registers (64 fp32/thread).
// h replicated in each CTA's smem, double-buffered; h_new broadcast via DSMEM.
// ================================================================================
__global__ void __cluster_dims__(NC, 1, 1) __launch_bounds__(SCAN_THREADS, 1)
scan_kernel(const float* __restrict__ Wh, const float* __restrict__ bh,
            const float* __restrict__ h0)
{
    cg::cluster_group cluster = cg::this_cluster();
    const unsigned crank = cluster.block_rank();

    __shared__ __align__(16) float h_s[2][DIM];
    __shared__ float hg_s[96];

    const int tid  = threadIdx.x;
    const int lane = tid & 31;
    const int warp = tid >> 5;
    const int col_local = warp * 8 + (lane & 7);   // 0..95
    const int q  = lane >> 3;                      // k-quarter 0..3
    const int qq = 2 * q;                          // bank-conflict rotation
    const int gate = col_local >> 5;               // 0=r,1=z,2=n
    const int m    = col_local & 31;
    const int gcol = gate * DIM + (int)crank * 32 + m;

    // ---- load this thread's 64 weights into registers, in rotated order ----
    float w[64];
#pragma unroll
    for (int j = 0; j < 16; ++j) {
        const int cidx = (j + qq) & 15;
        const int k = q * 64 + cidx * 4;
#pragma unroll
        for (int e = 0; e < 4; ++e)
            w[4 * j + e] = Wh[(k + e) * G3 + gcol];
    }
    const float bcol = bh[gcol];

    if (tid < DIM) h_s[0][tid] = h0[tid];

    // prefetch xg for t = 0 (gate threads only)
    float xr = 0.f, xz = 0.f, xn = 0.f;
    if (tid < 32) {
        const float* p = g_xg + (int)crank * 32 + tid;
        xr = p[0]; xz = p[DIM]; xn = p[2 * DIM];
    }

    cluster.sync();

#pragma unroll 1
    for (int t = 0; t < T_STEPS; ++t) {
        // ---- matvec: hg[col] = sum_k h[k] * Wh[k, gcol] ----
        const float4* hb = (const float4*)h_s[t & 1] + q * 16;
        float a0 = 0.f, a1 = 0.f, a2 = 0.f, a3 = 0.f;
#pragma unroll
        for (int j = 0; j < 16; ++j) {
            const int idx = (j + qq) & 15;       // conflict-free rotation
            const float4 hv = hb[idx];
            a0 = fmaf(w[4 * j + 0], hv.x, a0);
            a1 = fmaf(w[4 * j + 1], hv.y, a1);
            a2 = fmaf(w[4 * j + 2], hv.z, a2);
            a3 = fmaf(w[4 * j + 3], hv.w, a3);
        }
        float acc = (a0 + a1) + (a2 + a3);
        acc += __shfl_down_sync(0xffffffffu, acc, 16);
        acc += __shfl_down_sync(0xffffffffu, acc, 8);
        if (q == 0) hg_s[col_local] = acc + bcol;
        __syncthreads();

        // ---- gates + state update for our 32 h elements ----
        if (tid < 32) {
            const float hr = hg_s[tid];
            const float hz = hg_s[32 + tid];
            const float hn = hg_s[64 + tid];
            const float r = sigmoid_fast(xr + hr);
            const float z = sigmoid_fast(xz + hz);
            const float nn = tanh_fast(xn + r * hn);
            const float hold = h_s[t & 1][(int)crank * 32 + tid];
            const float hnew = (1.f - z) * nn + z * hold;

            g_ys[t * DIM + (int)crank * 32 + tid] = hnew;

            // prefetch next step's xg (hides DRAM latency behind next matvec)
            if (t + 1 < T_STEPS) {
                const float* p = g_xg + (t + 1) * G3 + (int)crank * 32 + tid;
                xr = p[0]; xz = p[DIM]; xn = p[2 * DIM];
            }

            // broadcast h_new to all CTAs (incl. self) into the other buffer
            const int nb = (t + 1) & 1;
#pragma unroll
            for (int d = 0; d < NC; ++d) {
                float* dst = cluster.map_shared_rank(&h_s[nb][(int)crank * 32 + tid], d);
                *dst = hnew;
            }
        }
        cluster.sync();   // release stores / acquire before next-step reads
    }
}

// ================================================================================
// Generic fp32 tiled GEMM: C[M,N] = op(A)[M,K] @ B[K,N] (+bias) (+relu)
// BM=BN=128, BK=8, 256 threads, 8x8 micro-tile. M,N,K multiples of tile dims.
// ================================================================================
__global__ __launch_bounds__(256)
void gemm_kernel(const float* __restrict__ A, const float* __restrict__ B,
                 const float* __restrict__ bias, float* __restrict__ C,
                 int M, int N, int K, int reluA, int reluOut)
{
    constexpr int BM = 128, BN = 128, BK = 8;
    __shared__ float As[BK][BM];
    __shared__ float Bs[BK][BN];

    const int tid = threadIdx.x;
    const int bm = blockIdx.y * BM;
    const int bn = blockIdx.x * BN;
    const int tx = tid & 15;        // 16 col groups
    const int ty = tid >> 4;        // 16 row groups

    const int aRow = tid >> 1;
    const int aCol = (tid & 1) * 4;
    const int bRow = tid >> 5;
    const int bCol = (tid & 31) * 4;

    const float* Aptr = A + (size_t)(bm + aRow) * K + aCol;
    const float* Bptr = B + (size_t)bRow * N + bn + bCol;

    float acc[8][8];
#pragma unroll
    for (int i = 0; i < 8; ++i)
#pragma unroll
        for (int j = 0; j < 8; ++j) acc[i][j] = 0.f;

    for (int k0 = 0; k0 < K; k0 += BK) {
        float4 av = *(const float4*)(Aptr + k0);
        if (reluA) {
            av.x = fmaxf(av.x, 0.f); av.y = fmaxf(av.y, 0.f);
            av.z = fmaxf(av.z, 0.f); av.w = fmaxf(av.w, 0.f);
        }
        As[aCol + 0][aRow] = av.x;
        As[aCol + 1][aRow] = av.y;
        As[aCol + 2][aRow] = av.z;
        As[aCol + 3][aRow] = av.w;
        *(float4*)&Bs[bRow][bCol] = *(const float4*)(Bptr + (size_t)k0 * N);
        __syncthreads();

#pragma unroll
        for (int k = 0; k < BK; ++k) {
            float a[8], b[8];
            *(float4*)(a)     = *(const float4*)&As[k][ty * 8];
            *(float4*)(a + 4) = *(const float4*)&As[k][ty * 8 + 4];
            *(float4*)(b)     = *(const float4*)&Bs[k][tx * 8];
            *(float4*)(b + 4) = *(const float4*)&Bs[k][tx * 8 + 4];
#pragma unroll
            for (int i = 0; i < 8; ++i)
#pragma unroll
                for (int j = 0; j < 8; ++j)
                    acc[i][j] = fmaf(a[i], b[j], acc[i][j]);
        }
        __syncthreads();
    }

    float bias_r[8];
#pragma unroll
    for (int j = 0; j < 8; ++j) bias_r[j] = bias ? bias[bn + tx * 8 + j] : 0.f;

#pragma unroll
    for (int i = 0; i < 8; ++i) {
        const int row = bm + ty * 8 + i;
        float* cp = C + (size_t)row * N + bn + tx * 8;
        float4 o0, o1;
        float v;
        v = acc[i][0] + bias_r[0]; o0.x = reluOut ? fmaxf(v, 0.f) : v;
        v = acc[i][1] + bias_r[1]; o0.y = reluOut ? fmaxf(v, 0.f) : v;
        v = acc[i][2] + bias_r[2]; o0.z = reluOut ? fmaxf(v, 0.f) : v;
        v = acc[i][3] + bias_r[3]; o0.w = reluOut ? fmaxf(v, 0.f) : v;
        v = acc[i][4] + bias_r[4]; o1.x = reluOut ? fmaxf(v, 0.f) : v;
        v = acc[i][5] + bias_r[5]; o1.y = reluOut ? fmaxf(v, 0.f) : v;
        v = acc[i][6] + bias_r[6]; o1.z = reluOut ? fmaxf(v, 0.f) : v;
        v = acc[i][7] + bias_r[7]; o1.w = reluOut ? fmaxf(v, 0.f) : v;
        *(float4*)cp = o0;
        *(float4*)(cp + 4) = o1;
    }
}

// ================================================================================
// Fused residual + LayerNorm over rows of 256: out = LN(base + delta)*g + b
// one warp per row, 8 rows per 256-thread CTA.
// ================================================================================
__global__ __launch_bounds__(256)
void ln_kernel(const float* __restrict__ base, const float* __restrict__ delta,
               const float* __restrict__ g, const float* __restrict__ b,
               float* __restrict__ out)
{
    const int row  = blockIdx.x * 8 + (threadIdx.x >> 5);
    const int lane = threadIdx.x & 31;

    const float4* bp = (const float4*)(base  + (size_t)row * DIM);
    const float4* dp = (const float4*)(delta + (size_t)row * DIM);
    float4 x0 = bp[lane],      d0 = dp[lane];
    float4 x1 = bp[32 + lane], d1 = dp[32 + lane];
    float4 u0, u1;
    u0.x = x0.x + d0.x; u0.y = x0.y + d0.y; u0.z = x0.z + d0.z; u0.w = x0.w + d0.w;
    u1.x = x1.x + d1.x; u1.y = x1.y + d1.y; u1.z = x1.z + d1.z; u1.w = x1.w + d1.w;

    float s  = u0.x + u0.y + u0.z + u0.w + u1.x + u1.y + u1.z + u1.w;
    float ss = u0.x*u0.x + u0.y*u0.y + u0.z*u0.z + u0.w*u0.w
             + u1.x*u1.x + u1.y*u1.y + u1.z*u1.z + u1.w*u1.w;
#pragma unroll
    for (int o = 16; o > 0; o >>= 1) {
        s  += __shfl_xor_sync(0xffffffffu, s, o);
        ss += __shfl_xor_sync(0xffffffffu, ss, o);
    }
    const float mean = s * (1.f / DIM);
    const float var  = ss * (1.f / DIM) - mean * mean;
    const float rstd = rsqrtf(var + 1e-6f);

    const float4 gv0 = ((const float4*)g)[lane];
    const float4 gv1 = ((const float4*)g)[32 + lane];
    const float4 bv0 = ((const float4*)b)[lane];
    const float4 bv1 = ((const float4*)b)[32 + lane];

    float4 o0, o1;
    o0.x = (u0.x - mean) * rstd * gv0.x + bv0.x;
    o0.y = (u0.y - mean) * rstd * gv0.y + bv0.y;
    o0.z = (u0.z - mean) * rstd * gv0.z + bv0.z;
    o0.w = (u0.w - mean) * rstd * gv0.w + bv0.w;
    o1.x = (u1.x - mean) * rstd * gv1.x + bv1.x;
    o1.y = (u1.y - mean) * rstd * gv1.y + bv1.y;
    o1.z = (u1.z - mean) * rstd * gv1.z + bv1.z;
    o1.w = (u1.w - mean) * rstd * gv1.w + bv1.w;

    float4* op = (float4*)(out + (size_t)row * DIM);
    op[lane] = o0;
    op[32 + lane] = o1;
}

// ================================================================================
extern "C" void kernel_launch(void* const* d_in, const int* in_sizes, int n_in,
                              void* d_out, int out_size)
{
    (void)in_sizes; (void)n_in; (void)out_size;
    const float* xs  = (const float*)d_in[0];
    const float* h0  = (const float*)d_in[1];
    const float* Wi  = (const float*)d_in[2];
    const float* Wh  = (const float*)d_in[3];
    const float* bh  = (const float*)d_in[4];
    const float* Wg  = (const float*)d_in[5];
    const float* bg  = (const float*)d_in[6];
    const float* g1  = (const float*)d_in[7];
    const float* be1 = (const float*)d_in[8];
    const float* W1  = (const float*)d_in[9];
    const float* b1  = (const float*)d_in[10];
    const float* W2  = (const float*)d_in[11];
    const float* b2  = (const float*)d_in[12];
    const float* g2  = (const float*)d_in[13];
    const float* be2 = (const float*)d_in[14];
    float* out = (float*)d_out;

    float *xg, *ys, *t3, *y, *t1, *t6;
    cudaGetSymbolAddress((void**)&xg, g_xg);
    cudaGetSymbolAddress((void**)&ys, g_ys);
    cudaGetSymbolAddress((void**)&t3, g_t3);
    cudaGetSymbolAddress((void**)&y,  g_y);
    cudaGetSymbolAddress((void**)&t1, g_t1);
    cudaGetSymbolAddress((void**)&t6, g_t6);

    // 1) xg = xs @ Wi                        [32768,256]@[256,768]
    gemm_kernel<<<dim3(G3 / 128, T_STEPS / 128), 256>>>(xs, Wi, nullptr, xg,
                                                        T_STEPS, G3, DIM, 0, 0);
    // 2) sequential GRU scan -> ys
    scan_kernel<<<NC, SCAN_THREADS>>>(Wh, bh, h0);
    // 3) t3 = relu(ys) @ Wg + bg
    gemm_kernel<<<dim3(DIM / 128, T_STEPS / 128), 256>>>(ys, Wg, bg, t3,
                                                         T_STEPS, DIM, DIM, 1, 0);
    // 4) y = LN(xs + t3) * g1 + be1
    ln_kernel<<<T_STEPS / 8, 256>>>(xs, t3, g1, be1, y);
    // 5) t1 = relu(y @ W1 + b1)
    gemm_kernel<<<dim3(FFN_DIM / 128, T_STEPS / 128), 256>>>(y, W1, b1, t1,
                                                             T_STEPS, FFN_DIM, DIM, 0, 1);
    // 6) t6 = t1 @ W2 + b2
    gemm_kernel<<<dim3(DIM / 128, T_STEPS / 128), 256>>>(t1, W2, b2, t6,
                                                         T_STEPS, DIM, FFN_DIM, 0, 0);
    // 7) out = LN(y + t6) * g2 + be2
    ln_kernel<<<T_STEPS / 8, 256>>>(y, t6, g2, be2, out);
}